// round 1
// baseline (speedup 1.0000x reference)
#include <cuda_runtime.h>
#include <cuda_bf16.h>
#include <math.h>

// ---------------------------------------------------------------------------
// Problem constants
// ---------------------------------------------------------------------------
#define B_SZ    2
#define S_LEN   2048
#define D_IN    2048
#define D_OUT   2048
#define NHEAD   16
#define DH      128
#define D3      6144          // 3 * D_OUT
#define M_TOK   (B_SZ * S_LEN)   // 4096 tokens

// Scratch (allocation-free rule: __device__ globals)
__device__ float g_qkv[(size_t)M_TOK * D3];     // 96 MB
__device__ float g_attn[(size_t)M_TOK * D_OUT]; // 32 MB

// ---------------------------------------------------------------------------
// packed f32x2 helpers (Blackwell fma.rn.f32x2 — 2 fp32 FMAs per instruction)
// ---------------------------------------------------------------------------
__device__ __forceinline__ unsigned long long pack2(float x, float y) {
    unsigned long long r;
    asm("mov.b64 %0, {%1, %2};" : "=l"(r) : "f"(x), "f"(y));
    return r;
}
__device__ __forceinline__ void fma2(unsigned long long& c,
                                     unsigned long long a,
                                     unsigned long long b) {
    asm("fma.rn.f32x2 %0, %1, %2, %0;" : "+l"(c) : "l"(a), "l"(b));
}
__device__ __forceinline__ void mul2(unsigned long long& c, unsigned long long a) {
    asm("mul.rn.f32x2 %0, %0, %1;" : "+l"(c) : "l"(a));
}
__device__ __forceinline__ float2 unpack2(unsigned long long v) {
    float2 r;
    asm("mov.b64 {%0, %1}, %2;" : "=f"(r.x), "=f"(r.y) : "l"(v));
    return r;
}

// ---------------------------------------------------------------------------
// GEMM: C[M,N] = A[M,K] @ B[N,K]^T (+ bias), all row-major, K contiguous.
// 128x128 block tile, BK=8, 256 threads, 8x8 per-thread microtile via f32x2.
// M,N,K assumed multiples of 128/8 (true for all three uses).
// ---------------------------------------------------------------------------
__global__ __launch_bounds__(256, 2)
void sgemm_nt(const float* __restrict__ A, const float* __restrict__ B,
              const float* __restrict__ bias, float* __restrict__ C,
              int M, int N, int K)
{
    __shared__ float As[8][128];
    __shared__ float Bs[8][128];

    const int t  = threadIdx.x;
    const int tx = t & 15;        // 0..15 -> N micro
    const int ty = t >> 4;        // 0..15 -> M micro
    const int m0 = blockIdx.y << 7;
    const int n0 = blockIdx.x << 7;

    const int lrow = t >> 1;          // 0..127
    const int lk   = (t & 1) << 2;    // 0 or 4
    const float* Ap = A + (size_t)(m0 + lrow) * K + lk;
    const float* Bp = B + (size_t)(n0 + lrow) * K + lk;

    unsigned long long c[8][4];
#pragma unroll
    for (int i = 0; i < 8; ++i)
#pragma unroll
        for (int j = 0; j < 4; ++j) c[i][j] = 0ull;

    for (int k0 = 0; k0 < K; k0 += 8) {
        float4 av = *(const float4*)(Ap + k0);
        float4 bv = *(const float4*)(Bp + k0);
        __syncthreads();
        As[lk + 0][lrow] = av.x; As[lk + 1][lrow] = av.y;
        As[lk + 2][lrow] = av.z; As[lk + 3][lrow] = av.w;
        Bs[lk + 0][lrow] = bv.x; Bs[lk + 1][lrow] = bv.y;
        Bs[lk + 2][lrow] = bv.z; Bs[lk + 3][lrow] = bv.w;
        __syncthreads();

#pragma unroll
        for (int kk = 0; kk < 8; ++kk) {
            float4 a0 = *(const float4*)&As[kk][ty * 8];
            float4 a1 = *(const float4*)&As[kk][ty * 8 + 4];
            float4 b0 = *(const float4*)&Bs[kk][tx * 8];
            float4 b1 = *(const float4*)&Bs[kk][tx * 8 + 4];
            unsigned long long bb[4] = {
                pack2(b0.x, b0.y), pack2(b0.z, b0.w),
                pack2(b1.x, b1.y), pack2(b1.z, b1.w)
            };
            float aa[8] = {a0.x, a0.y, a0.z, a0.w, a1.x, a1.y, a1.z, a1.w};
#pragma unroll
            for (int i = 0; i < 8; ++i) {
                unsigned long long ap = pack2(aa[i], aa[i]);
#pragma unroll
                for (int j = 0; j < 4; ++j) fma2(c[i][j], ap, bb[j]);
            }
        }
    }

#pragma unroll
    for (int i = 0; i < 8; ++i) {
        const int row = m0 + ty * 8 + i;
#pragma unroll
        for (int j = 0; j < 4; ++j) {
            const int col = n0 + tx * 8 + j * 2;
            float2 v = unpack2(c[i][j]);
            if (bias) { v.x += bias[col]; v.y += bias[col + 1]; }
            *(float2*)(C + (size_t)row * N + col) = v;
        }
    }
}

// ---------------------------------------------------------------------------
// Fused causal flash attention.
// Grid: (S/128 q-tiles, B*H). Block: 256 threads = 8 warps, 16 q-rows/warp.
// Each lane owns 2 key-cols (scores) and 4 out-cols (O accumulate).
// qkv layout per token: [q(2048) | k(2048) | v(2048)], head h at h*128.
// ---------------------------------------------------------------------------
#define BQ   128
#define BKV  64
#define KTP  66    // padded d-major K stride (floats)

__global__ __launch_bounds__(256, 1)
void attn_kernel(const float* __restrict__ qkv, float* __restrict__ out)
{
    extern __shared__ float sm[];
    float* Qs = sm;                     // 128*128
    float* Kt = Qs + BQ * DH;           // 128*66 (d-major, padded)
    float* Vs = Kt + DH * KTP;          // 64*128
    float* Ps = Vs + BKV * DH;          // 128*64

    const int t = threadIdx.x, w = t >> 5, l = t & 31;
    const int qtile = (int)gridDim.x - 1 - (int)blockIdx.x;  // heavy tiles first
    const int bh = blockIdx.y;
    const int b = bh >> 4, h = bh & 15;
    const int qt0 = qtile * BQ;
    const float scale = 0.08838834764831843f;  // 1/sqrt(128)

    // Load Q tile (pre-scaled)
    {
        const int row = t >> 1, d0 = (t & 1) * 64;
        const float* gq = qkv + (size_t)(b * S_LEN + qt0 + row) * D3 + h * DH + d0;
        float* sq = Qs + row * DH + d0;
#pragma unroll
        for (int f = 0; f < 16; ++f) {
            float4 v = *(const float4*)(gq + f * 4);
            v.x *= scale; v.y *= scale; v.z *= scale; v.w *= scale;
            *(float4*)(sq + f * 4) = v;
        }
    }

    unsigned long long Oa[16], Ob[16];
    float mr[16], lr[16];
#pragma unroll
    for (int r = 0; r < 16; ++r) {
        Oa[r] = 0ull; Ob[r] = 0ull; mr[r] = -INFINITY; lr[r] = 0.f;
    }

    const int nkt = (qt0 + BQ) / BKV;   // causal: only tiles up to diagonal
    for (int kt = 0; kt < nkt; ++kt) {
        __syncthreads();  // previous iteration done reading Kt/Vs
        // Load K (d-major transposed) and V (row-major)
        {
            const int j = t >> 2, d0 = (t & 3) * 32;
            const float* gk = qkv + (size_t)(b * S_LEN + kt * BKV + j) * D3
                              + D_OUT + h * DH + d0;
            const float* gv = gk + D_OUT;
#pragma unroll
            for (int f = 0; f < 8; ++f) {
                const int d = d0 + f * 4;
                float4 kv = *(const float4*)(gk + f * 4);
                Kt[(d + 0) * KTP + j] = kv.x;
                Kt[(d + 1) * KTP + j] = kv.y;
                Kt[(d + 2) * KTP + j] = kv.z;
                Kt[(d + 3) * KTP + j] = kv.w;
                float4 vv = *(const float4*)(gv + f * 4);
                *(float4*)(Vs + j * DH + d) = vv;
            }
        }
        __syncthreads();

        // Warps whose rows are entirely above this key tile: nothing to do
        const bool active = (kt * BKV) <= (qt0 + w * 16 + 15);
        if (active) {
            // Scores: acc[r] = Q[row] . K[col 2l], K[col 2l+1]
            float2 acc[16];
#pragma unroll
            for (int r = 0; r < 16; ++r) acc[r] = make_float2(0.f, 0.f);
            const float* qrow = Qs + (w * 16) * DH;
            for (int d = 0; d < DH; ++d) {
                float2 k2 = *(const float2*)(Kt + d * KTP + l * 2);
#pragma unroll
                for (int r = 0; r < 16; ++r) {
                    float q = qrow[r * DH + d];
                    acc[r].x += q * k2.x;
                    acc[r].y += q * k2.y;
                }
            }

            // Online softmax update + write P tile (warp-local rows)
#pragma unroll
            for (int r = 0; r < 16; ++r) {
                const int qg = qt0 + w * 16 + r;
                const int kg = kt * BKV + l * 2;
                float2 s = acc[r];
                if (kg > qg)     s.x = -1e30f;
                if (kg + 1 > qg) s.y = -1e30f;
                float rmax = fmaxf(s.x, s.y);
#pragma unroll
                for (int off = 16; off; off >>= 1)
                    rmax = fmaxf(rmax, __shfl_xor_sync(0xffffffffu, rmax, off));
                const float mnew  = fmaxf(mr[r], rmax);
                const float alpha = __expf(mr[r] - mnew);
                const float p0 = __expf(s.x - mnew);
                const float p1 = __expf(s.y - mnew);
                float ps = p0 + p1;
#pragma unroll
                for (int off = 16; off; off >>= 1)
                    ps += __shfl_xor_sync(0xffffffffu, ps, off);
                lr[r] = lr[r] * alpha + ps;
                mr[r] = mnew;
                unsigned long long al = pack2(alpha, alpha);
                mul2(Oa[r], al);
                mul2(Ob[r], al);
                *(float2*)(Ps + (w * 16 + r) * 64 + l * 2) = make_float2(p0, p1);
            }
            __syncwarp();

            // O += P @ V   (lane owns out cols l*4 .. l*4+3)
            const float* prow = Ps + (w * 16) * 64;
            for (int j = 0; j < BKV; ++j) {
                float4 v = *(const float4*)(Vs + j * DH + l * 4);
                unsigned long long v01 = pack2(v.x, v.y);
                unsigned long long v23 = pack2(v.z, v.w);
#pragma unroll
                for (int r = 0; r < 16; ++r) {
                    float p = prow[r * 64 + j];
                    unsigned long long pp = pack2(p, p);
                    fma2(Oa[r], pp, v01);
                    fma2(Ob[r], pp, v23);
                }
            }
        }
    }

    // Epilogue: normalize and write [B,S,H*Dh]
#pragma unroll
    for (int r = 0; r < 16; ++r) {
        const float inv = 1.0f / lr[r];
        const int qg = qt0 + w * 16 + r;
        float2 a = unpack2(Oa[r]);
        float2 bv = unpack2(Ob[r]);
        float4 o;
        o.x = a.x * inv;  o.y = a.y * inv;
        o.z = bv.x * inv; o.w = bv.y * inv;
        *(float4*)(out + (size_t)(b * S_LEN + qg) * D_OUT + h * DH + l * 4) = o;
    }
}

// ---------------------------------------------------------------------------
// Launch
// ---------------------------------------------------------------------------
extern "C" void kernel_launch(void* const* d_in, const int* in_sizes, int n_in,
                              void* d_out, int out_size)
{
    const float* x      = (const float*)d_in[0];
    const float* w_qkv  = (const float*)d_in[1];
    const float* w_proj = (const float*)d_in[2];
    const float* b_proj = (const float*)d_in[3];
    float* out = (float*)d_out;

    void* qkvp = nullptr; void* attnp = nullptr;
    cudaGetSymbolAddress(&qkvp, g_qkv);
    cudaGetSymbolAddress(&attnp, g_attn);
    float* qkv  = (float*)qkvp;
    float* attn = (float*)attnp;

    const int ATTN_SMEM = (BQ * DH + DH * KTP + BKV * DH + BQ * 64) * 4;  // 164864 B
    cudaFuncSetAttribute(attn_kernel,
                         cudaFuncAttributeMaxDynamicSharedMemorySize, ATTN_SMEM);

    // 1) QKV projection: [4096,6144] = x[4096,2048] @ w_qkv[6144,2048]^T
    sgemm_nt<<<dim3(D3 / 128, M_TOK / 128), 256>>>(x, w_qkv, nullptr, qkv,
                                                   M_TOK, D3, D_IN);
    // 2) Fused causal attention -> [B,S,2048]
    attn_kernel<<<dim3(S_LEN / BQ, B_SZ * NHEAD), 256, ATTN_SMEM>>>(qkv, attn);
    // 3) Output projection + bias -> d_out
    sgemm_nt<<<dim3(D_OUT / 128, M_TOK / 128), 256>>>(attn, w_proj, b_proj, out,
                                                      M_TOK, D_OUT, D_OUT);
}

// round 3
// speedup vs baseline: 1.3896x; 1.3896x over previous
#include <cuda_runtime.h>
#include <cuda_bf16.h>
#include <math.h>
#include <stdint.h>

// ---------------------------------------------------------------------------
// Problem constants
// ---------------------------------------------------------------------------
#define B_SZ    2
#define S_LEN   2048
#define D_IN    2048
#define D_OUT   2048
#define NHEAD   16
#define DH      128
#define D3      6144
#define M_TOK   (B_SZ * S_LEN)

// Scratch
__device__ float g_qkv[(size_t)M_TOK * D3];
__device__ float g_attn[(size_t)M_TOK * D_OUT];

// ---------------------------------------------------------------------------
// Helpers
// ---------------------------------------------------------------------------
__device__ __forceinline__ uint32_t smem_u32(const void* p) {
    uint32_t a;
    asm("{ .reg .u64 t; cvta.to.shared.u64 t, %1; cvt.u32.u64 %0, t; }" : "=r"(a) : "l"(p));
    return a;
}

// packed f32x2 helpers (attention kernel)
__device__ __forceinline__ unsigned long long pack2(float x, float y) {
    unsigned long long r;
    asm("mov.b64 %0, {%1, %2};" : "=l"(r) : "f"(x), "f"(y));
    return r;
}
__device__ __forceinline__ void fma2(unsigned long long& c, unsigned long long a, unsigned long long b) {
    asm("fma.rn.f32x2 %0, %1, %2, %0;" : "+l"(c) : "l"(a), "l"(b));
}
__device__ __forceinline__ void mul2(unsigned long long& c, unsigned long long a) {
    asm("mul.rn.f32x2 %0, %0, %1;" : "+l"(c) : "l"(a));
}
__device__ __forceinline__ float2 unpack2(unsigned long long v) {
    float2 r;
    asm("mov.b64 {%0, %1}, %2;" : "=f"(r.x), "=f"(r.y) : "l"(v));
    return r;
}

// bf16 2-term split of a float pair -> packed hi bf16x2 + lo bf16x2
__device__ __forceinline__ void split2(float x, float y, uint32_t& hi, uint32_t& lo) {
    __nv_bfloat16 hx = __float2bfloat16(x);
    __nv_bfloat16 hy = __float2bfloat16(y);
    float rx = x - __bfloat162float(hx);
    float ry = y - __bfloat162float(hy);
    __nv_bfloat162 h2 = __halves2bfloat162(hx, hy);
    __nv_bfloat162 l2 = __halves2bfloat162(__float2bfloat16(rx), __float2bfloat16(ry));
    hi = *reinterpret_cast<uint32_t*>(&h2);
    lo = *reinterpret_cast<uint32_t*>(&l2);
}

// ldmatrix x4 (four 8x8 b16 tiles)
__device__ __forceinline__ void ldsm4(uint32_t* r, uint32_t addr) {
    asm volatile("ldmatrix.sync.aligned.m8n8.x4.shared.b16 {%0,%1,%2,%3}, [%4];"
                 : "=r"(r[0]), "=r"(r[1]), "=r"(r[2]), "=r"(r[3]) : "r"(addr));
}

// mma.sync m16n8k16 bf16 -> f32 accumulate
__device__ __forceinline__ void mma_bf16(float* c, const uint32_t* a, uint32_t b0, uint32_t b1) {
    asm volatile(
        "mma.sync.aligned.m16n8k16.row.col.f32.bf16.bf16.f32 "
        "{%0,%1,%2,%3}, {%4,%5,%6,%7}, {%8,%9}, {%0,%1,%2,%3};"
        : "+f"(c[0]), "+f"(c[1]), "+f"(c[2]), "+f"(c[3])
        : "r"(a[0]), "r"(a[1]), "r"(a[2]), "r"(a[3]), "r"(b0), "r"(b1));
}

// ---------------------------------------------------------------------------
// bf16-split tensor-core GEMM: C[M,N] = A[M,K] @ B[N,K]^T (+bias)
// Block tile 128x128, BK=32, 256 threads = 8 warps (4m x 2n), warp tile 32x64.
// 3-term split: Ah*Bh + Ah*Bl + Al*Bh  (fp32 accum in registers).
// smem: 4 tiles [128 rows x 32 bf16], padded row stride 40 bf16 (80 B).
// ---------------------------------------------------------------------------
#define GBK     32
#define SPAD    40                     // bf16 elems per smem row
#define ROWB    (SPAD * 2)             // 80 bytes
#define TILE_BY (128 * ROWB)           // 10240 bytes

__global__ __launch_bounds__(256, 1)
void mma_gemm(const float* __restrict__ A, const float* __restrict__ B,
              const float* __restrict__ bias, float* __restrict__ C,
              int M, int N, int K)
{
    __shared__ char smem[4 * TILE_BY];  // Ah | Al | Bh | Bl
    const uint32_t sb   = smem_u32(smem);
    const uint32_t sAh  = sb;
    const uint32_t sAl  = sb + TILE_BY;
    const uint32_t sBh  = sb + 2 * TILE_BY;
    const uint32_t sBl  = sb + 3 * TILE_BY;

    const int tid  = threadIdx.x;
    const int wid  = tid >> 5, lane = tid & 31;
    const int m0   = blockIdx.y << 7;
    const int n0   = blockIdx.x << 7;
    const int wm   = (wid & 3) * 32;    // warp m offset
    const int wn   = (wid >> 2) * 64;   // warp n offset

    // loader: 2 threads per row, 16 cols each
    const int lrow   = tid >> 1;
    const int lcol16 = (tid & 1) * 16;
    const float* Ap = A + (size_t)(m0 + lrow) * K + lcol16;
    const float* Bp = B + (size_t)(n0 + lrow) * K + lcol16;
    const uint32_t stoff = (uint32_t)lrow * ROWB + lcol16 * 2;

    // ldmatrix lane address components
    const uint32_t aoff = (uint32_t)(wm + (lane & 15)) * ROWB + (lane >> 4) * 16;
    const uint32_t boff = (uint32_t)(wn + (lane & 15)) * ROWB + (lane >> 4) * 16;

    float acc[2][8][4];
#pragma unroll
    for (int mt = 0; mt < 2; ++mt)
#pragma unroll
        for (int nb = 0; nb < 8; ++nb)
#pragma unroll
            for (int e = 0; e < 4; ++e) acc[mt][nb][e] = 0.f;

    const int nchunk = K / GBK;
    for (int i = 0; i < nchunk; ++i) {
        const int k0 = i * GBK;

        // prefetch gmem -> regs
        float4 a4[4], b4[4];
#pragma unroll
        for (int f = 0; f < 4; ++f) {
            a4[f] = *(const float4*)(Ap + k0 + f * 4);
            b4[f] = *(const float4*)(Bp + k0 + f * 4);
        }

        __syncthreads();   // previous chunk's compute done reading smem

        // convert + store bf16 hi/lo tiles
#pragma unroll
        for (int f = 0; f < 4; ++f) {
            uint32_t h0, l0, h1, l1;
            split2(a4[f].x, a4[f].y, h0, l0);
            split2(a4[f].z, a4[f].w, h1, l1);
            *(uint2*)(smem + (sAh - sb) + stoff + f * 8) = make_uint2(h0, h1);
            *(uint2*)(smem + (sAl - sb) + stoff + f * 8) = make_uint2(l0, l1);
            split2(b4[f].x, b4[f].y, h0, l0);
            split2(b4[f].z, b4[f].w, h1, l1);
            *(uint2*)(smem + (sBh - sb) + stoff + f * 8) = make_uint2(h0, h1);
            *(uint2*)(smem + (sBl - sb) + stoff + f * 8) = make_uint2(l0, l1);
        }
        __syncthreads();

        // compute: 2 k16 steps
#pragma unroll
        for (int ks = 0; ks < 2; ++ks) {
            uint32_t ah[2][4], al[2][4];
#pragma unroll
            for (int mt = 0; mt < 2; ++mt) {
                ldsm4(ah[mt], sAh + aoff + mt * 16 * ROWB + ks * 32);
                ldsm4(al[mt], sAl + aoff + mt * 16 * ROWB + ks * 32);
            }
#pragma unroll
            for (int pg = 0; pg < 4; ++pg) {
                uint32_t bh[4], bl[4];
                ldsm4(bh, sBh + boff + pg * 16 * ROWB + ks * 32);
                ldsm4(bl, sBl + boff + pg * 16 * ROWB + ks * 32);
#pragma unroll
                for (int mt = 0; mt < 2; ++mt) {
                    mma_bf16(acc[mt][pg * 2],     ah[mt], bh[0], bh[2]);
                    mma_bf16(acc[mt][pg * 2],     ah[mt], bl[0], bl[2]);
                    mma_bf16(acc[mt][pg * 2],     al[mt], bh[0], bh[2]);
                    mma_bf16(acc[mt][pg * 2 + 1], ah[mt], bh[1], bh[3]);
                    mma_bf16(acc[mt][pg * 2 + 1], ah[mt], bl[1], bl[3]);
                    mma_bf16(acc[mt][pg * 2 + 1], al[mt], bh[1], bh[3]);
                }
            }
        }
    }

    // epilogue: c0,c1 -> (row, col..col+1); c2,c3 -> (row+8, ...)
    const int crow = lane >> 2;
    const int ccol = (lane & 3) * 2;
#pragma unroll
    for (int mt = 0; mt < 2; ++mt) {
#pragma unroll
        for (int nb = 0; nb < 8; ++nb) {
            const int row = m0 + wm + mt * 16 + crow;
            const int col = n0 + wn + nb * 8 + ccol;
            float2 v0 = make_float2(acc[mt][nb][0], acc[mt][nb][1]);
            float2 v1 = make_float2(acc[mt][nb][2], acc[mt][nb][3]);
            if (bias) {
                float2 bv = *(const float2*)(bias + col);
                v0.x += bv.x; v0.y += bv.y;
                v1.x += bv.x; v1.y += bv.y;
            }
            *(float2*)(C + (size_t)row * N + col)       = v0;
            *(float2*)(C + (size_t)(row + 8) * N + col) = v1;
        }
    }
}

// ---------------------------------------------------------------------------
// Fused causal flash attention (unchanged, fp32 SIMT + f32x2)
// ---------------------------------------------------------------------------
#define BQ   128
#define BKV  64
#define KTP  66

__global__ __launch_bounds__(256, 1)
void attn_kernel(const float* __restrict__ qkv, float* __restrict__ out)
{
    extern __shared__ float sm[];
    float* Qs = sm;
    float* Kt = Qs + BQ * DH;
    float* Vs = Kt + DH * KTP;
    float* Ps = Vs + BKV * DH;

    const int t = threadIdx.x, w = t >> 5, l = t & 31;
    const int qtile = (int)gridDim.x - 1 - (int)blockIdx.x;
    const int bh = blockIdx.y;
    const int b = bh >> 4, h = bh & 15;
    const int qt0 = qtile * BQ;
    const float scale = 0.08838834764831843f;

    {
        const int row = t >> 1, d0 = (t & 1) * 64;
        const float* gq = qkv + (size_t)(b * S_LEN + qt0 + row) * D3 + h * DH + d0;
        float* sq = Qs + row * DH + d0;
#pragma unroll
        for (int f = 0; f < 16; ++f) {
            float4 v = *(const float4*)(gq + f * 4);
            v.x *= scale; v.y *= scale; v.z *= scale; v.w *= scale;
            *(float4*)(sq + f * 4) = v;
        }
    }

    unsigned long long Oa[16], Ob[16];
    float mr[16], lr[16];
#pragma unroll
    for (int r = 0; r < 16; ++r) {
        Oa[r] = 0ull; Ob[r] = 0ull; mr[r] = -INFINITY; lr[r] = 0.f;
    }

    const int nkt = (qt0 + BQ) / BKV;
    for (int kt = 0; kt < nkt; ++kt) {
        __syncthreads();
        {
            const int j = t >> 2, d0 = (t & 3) * 32;
            const float* gk = qkv + (size_t)(b * S_LEN + kt * BKV + j) * D3
                              + D_OUT + h * DH + d0;
            const float* gv = gk + D_OUT;
#pragma unroll
            for (int f = 0; f < 8; ++f) {
                const int d = d0 + f * 4;
                float4 kv = *(const float4*)(gk + f * 4);
                Kt[(d + 0) * KTP + j] = kv.x;
                Kt[(d + 1) * KTP + j] = kv.y;
                Kt[(d + 2) * KTP + j] = kv.z;
                Kt[(d + 3) * KTP + j] = kv.w;
                float4 vv = *(const float4*)(gv + f * 4);
                *(float4*)(Vs + j * DH + d) = vv;
            }
        }
        __syncthreads();

        const bool active = (kt * BKV) <= (qt0 + w * 16 + 15);
        if (active) {
            float2 acc[16];
#pragma unroll
            for (int r = 0; r < 16; ++r) acc[r] = make_float2(0.f, 0.f);
            const float* qrow = Qs + (w * 16) * DH;
            for (int d = 0; d < DH; ++d) {
                float2 k2 = *(const float2*)(Kt + d * KTP + l * 2);
#pragma unroll
                for (int r = 0; r < 16; ++r) {
                    float q = qrow[r * DH + d];
                    acc[r].x += q * k2.x;
                    acc[r].y += q * k2.y;
                }
            }

#pragma unroll
            for (int r = 0; r < 16; ++r) {
                const int qg = qt0 + w * 16 + r;
                const int kg = kt * BKV + l * 2;
                float2 s = acc[r];
                if (kg > qg)     s.x = -1e30f;
                if (kg + 1 > qg) s.y = -1e30f;
                float rmax = fmaxf(s.x, s.y);
#pragma unroll
                for (int off = 16; off; off >>= 1)
                    rmax = fmaxf(rmax, __shfl_xor_sync(0xffffffffu, rmax, off));
                const float mnew  = fmaxf(mr[r], rmax);
                const float alpha = __expf(mr[r] - mnew);
                const float p0 = __expf(s.x - mnew);
                const float p1 = __expf(s.y - mnew);
                float ps = p0 + p1;
#pragma unroll
                for (int off = 16; off; off >>= 1)
                    ps += __shfl_xor_sync(0xffffffffu, ps, off);
                lr[r] = lr[r] * alpha + ps;
                mr[r] = mnew;
                unsigned long long al = pack2(alpha, alpha);
                mul2(Oa[r], al);
                mul2(Ob[r], al);
                *(float2*)(Ps + (w * 16 + r) * 64 + l * 2) = make_float2(p0, p1);
            }
            __syncwarp();

            const float* prow = Ps + (w * 16) * 64;
            for (int j = 0; j < BKV; ++j) {
                float4 v = *(const float4*)(Vs + j * DH + l * 4);
                unsigned long long v01 = pack2(v.x, v.y);
                unsigned long long v23 = pack2(v.z, v.w);
#pragma unroll
                for (int r = 0; r < 16; ++r) {
                    float p = prow[r * 64 + j];
                    unsigned long long pp = pack2(p, p);
                    fma2(Oa[r], pp, v01);
                    fma2(Ob[r], pp, v23);
                }
            }
        }
    }

#pragma unroll
    for (int r = 0; r < 16; ++r) {
        const float inv = 1.0f / lr[r];
        const int qg = qt0 + w * 16 + r;
        float2 a = unpack2(Oa[r]);
        float2 bv = unpack2(Ob[r]);
        float4 o;
        o.x = a.x * inv;  o.y = a.y * inv;
        o.z = bv.x * inv; o.w = bv.y * inv;
        *(float4*)(out + (size_t)(b * S_LEN + qg) * D_OUT + h * DH + l * 4) = o;
    }
}

// ---------------------------------------------------------------------------
// Launch
// ---------------------------------------------------------------------------
extern "C" void kernel_launch(void* const* d_in, const int* in_sizes, int n_in,
                              void* d_out, int out_size)
{
    const float* x      = (const float*)d_in[0];
    const float* w_qkv  = (const float*)d_in[1];
    const float* w_proj = (const float*)d_in[2];
    const float* b_proj = (const float*)d_in[3];
    float* out = (float*)d_out;

    void* qkvp = nullptr; void* attnp = nullptr;
    cudaGetSymbolAddress(&qkvp, g_qkv);
    cudaGetSymbolAddress(&attnp, g_attn);
    float* qkv  = (float*)qkvp;
    float* attn = (float*)attnp;

    const int ATTN_SMEM = (BQ * DH + DH * KTP + BKV * DH + BQ * 64) * 4;
    cudaFuncSetAttribute(attn_kernel,
                         cudaFuncAttributeMaxDynamicSharedMemorySize, ATTN_SMEM);

    // 1) QKV projection: [4096,6144] = x @ w_qkv^T
    mma_gemm<<<dim3(D3 / 128, M_TOK / 128), 256>>>(x, w_qkv, nullptr, qkv,
                                                   M_TOK, D3, D_IN);
    // 2) Fused causal attention
    attn_kernel<<<dim3(S_LEN / BQ, B_SZ * NHEAD), 256, ATTN_SMEM>>>(qkv, attn);
    // 3) Output projection + bias
    mma_gemm<<<dim3(D_OUT / 128, M_TOK / 128), 256>>>(attn, w_proj, b_proj, out,
                                                      M_TOK, D_OUT, D_OUT);
}

// round 4
// speedup vs baseline: 2.2383x; 1.6107x over previous
#include <cuda_runtime.h>
#include <cuda_bf16.h>
#include <math.h>
#include <stdint.h>

// ---------------------------------------------------------------------------
// Problem constants
// ---------------------------------------------------------------------------
#define B_SZ    2
#define S_LEN   2048
#define D_IN    2048
#define D_OUT   2048
#define NHEAD   16
#define DH      128
#define D3      6144
#define M_TOK   (B_SZ * S_LEN)

// Scratch
__device__ float g_qkv[(size_t)M_TOK * D3];
__device__ float g_attn[(size_t)M_TOK * D_OUT];

// ---------------------------------------------------------------------------
// Helpers
// ---------------------------------------------------------------------------
__device__ __forceinline__ uint32_t smem_u32(const void* p) {
    uint32_t a;
    asm("{ .reg .u64 t; cvta.to.shared.u64 t, %1; cvt.u32.u64 %0, t; }" : "=r"(a) : "l"(p));
    return a;
}

// bf16 2-term split of a float pair -> packed hi bf16x2 + lo bf16x2
__device__ __forceinline__ void split2(float x, float y, uint32_t& hi, uint32_t& lo) {
    __nv_bfloat16 hx = __float2bfloat16(x);
    __nv_bfloat16 hy = __float2bfloat16(y);
    float rx = x - __bfloat162float(hx);
    float ry = y - __bfloat162float(hy);
    __nv_bfloat162 h2 = __halves2bfloat162(hx, hy);
    __nv_bfloat162 l2 = __halves2bfloat162(__float2bfloat16(rx), __float2bfloat16(ry));
    hi = *reinterpret_cast<uint32_t*>(&h2);
    lo = *reinterpret_cast<uint32_t*>(&l2);
}

// ldmatrix x4 (four 8x8 b16 tiles)
__device__ __forceinline__ void ldsm4(uint32_t* r, uint32_t addr) {
    asm volatile("ldmatrix.sync.aligned.m8n8.x4.shared.b16 {%0,%1,%2,%3}, [%4];"
                 : "=r"(r[0]), "=r"(r[1]), "=r"(r[2]), "=r"(r[3]) : "r"(addr));
}

// mma.sync m16n8k16 bf16 -> f32 accumulate
__device__ __forceinline__ void mma_bf16(float* c, const uint32_t* a, uint32_t b0, uint32_t b1) {
    asm volatile(
        "mma.sync.aligned.m16n8k16.row.col.f32.bf16.bf16.f32 "
        "{%0,%1,%2,%3}, {%4,%5,%6,%7}, {%8,%9}, {%0,%1,%2,%3};"
        : "+f"(c[0]), "+f"(c[1]), "+f"(c[2]), "+f"(c[3])
        : "r"(a[0]), "r"(a[1]), "r"(a[2]), "r"(a[3]), "r"(b0), "r"(b1));
}

// ---------------------------------------------------------------------------
// bf16-split tensor-core GEMM: C[M,N] = A[M,K] @ B[N,K]^T (+bias)
// ---------------------------------------------------------------------------
#define GBK     32
#define SPAD    40
#define ROWB    (SPAD * 2)             // 80 bytes
#define TILE_BY (128 * ROWB)           // 10240 bytes

__global__ __launch_bounds__(256, 2)
void mma_gemm(const float* __restrict__ A, const float* __restrict__ B,
              const float* __restrict__ bias, float* __restrict__ C,
              int M, int N, int K)
{
    __shared__ char smem[4 * TILE_BY];  // Ah | Al | Bh | Bl
    const uint32_t sb   = smem_u32(smem);
    const uint32_t sAh  = sb;
    const uint32_t sAl  = sb + TILE_BY;
    const uint32_t sBh  = sb + 2 * TILE_BY;
    const uint32_t sBl  = sb + 3 * TILE_BY;

    const int tid  = threadIdx.x;
    const int wid  = tid >> 5, lane = tid & 31;
    const int m0   = blockIdx.y << 7;
    const int n0   = blockIdx.x << 7;
    const int wm   = (wid & 3) * 32;
    const int wn   = (wid >> 2) * 64;

    const int lrow   = tid >> 1;
    const int lcol16 = (tid & 1) * 16;
    const float* Ap = A + (size_t)(m0 + lrow) * K + lcol16;
    const float* Bp = B + (size_t)(n0 + lrow) * K + lcol16;
    const uint32_t stoff = (uint32_t)lrow * ROWB + lcol16 * 2;

    const uint32_t aoff = (uint32_t)(wm + (lane & 15)) * ROWB + (lane >> 4) * 16;
    const uint32_t boff = (uint32_t)(wn + (lane & 15)) * ROWB + (lane >> 4) * 16;

    float acc[2][8][4];
#pragma unroll
    for (int mt = 0; mt < 2; ++mt)
#pragma unroll
        for (int nb = 0; nb < 8; ++nb)
#pragma unroll
            for (int e = 0; e < 4; ++e) acc[mt][nb][e] = 0.f;

    const int nchunk = K / GBK;
    for (int i = 0; i < nchunk; ++i) {
        const int k0 = i * GBK;
        float4 a4[4], b4[4];
#pragma unroll
        for (int f = 0; f < 4; ++f) {
            a4[f] = *(const float4*)(Ap + k0 + f * 4);
            b4[f] = *(const float4*)(Bp + k0 + f * 4);
        }
        __syncthreads();
#pragma unroll
        for (int f = 0; f < 4; ++f) {
            uint32_t h0, l0, h1, l1;
            split2(a4[f].x, a4[f].y, h0, l0);
            split2(a4[f].z, a4[f].w, h1, l1);
            *(uint2*)(smem + (sAh - sb) + stoff + f * 8) = make_uint2(h0, h1);
            *(uint2*)(smem + (sAl - sb) + stoff + f * 8) = make_uint2(l0, l1);
            split2(b4[f].x, b4[f].y, h0, l0);
            split2(b4[f].z, b4[f].w, h1, l1);
            *(uint2*)(smem + (sBh - sb) + stoff + f * 8) = make_uint2(h0, h1);
            *(uint2*)(smem + (sBl - sb) + stoff + f * 8) = make_uint2(l0, l1);
        }
        __syncthreads();

#pragma unroll
        for (int ks = 0; ks < 2; ++ks) {
            uint32_t ah[2][4], al[2][4];
#pragma unroll
            for (int mt = 0; mt < 2; ++mt) {
                ldsm4(ah[mt], sAh + aoff + mt * 16 * ROWB + ks * 32);
                ldsm4(al[mt], sAl + aoff + mt * 16 * ROWB + ks * 32);
            }
#pragma unroll
            for (int pg = 0; pg < 4; ++pg) {
                uint32_t bh[4], bl[4];
                ldsm4(bh, sBh + boff + pg * 16 * ROWB + ks * 32);
                ldsm4(bl, sBl + boff + pg * 16 * ROWB + ks * 32);
#pragma unroll
                for (int mt = 0; mt < 2; ++mt) {
                    mma_bf16(acc[mt][pg * 2],     ah[mt], bh[0], bh[2]);
                    mma_bf16(acc[mt][pg * 2],     ah[mt], bl[0], bl[2]);
                    mma_bf16(acc[mt][pg * 2],     al[mt], bh[0], bh[2]);
                    mma_bf16(acc[mt][pg * 2 + 1], ah[mt], bh[1], bh[3]);
                    mma_bf16(acc[mt][pg * 2 + 1], ah[mt], bl[1], bl[3]);
                    mma_bf16(acc[mt][pg * 2 + 1], al[mt], bh[1], bh[3]);
                }
            }
        }
    }

    const int crow = lane >> 2;
    const int ccol = (lane & 3) * 2;
#pragma unroll
    for (int mt = 0; mt < 2; ++mt) {
#pragma unroll
        for (int nb = 0; nb < 8; ++nb) {
            const int row = m0 + wm + mt * 16 + crow;
            const int col = n0 + wn + nb * 8 + ccol;
            float2 v0 = make_float2(acc[mt][nb][0], acc[mt][nb][1]);
            float2 v1 = make_float2(acc[mt][nb][2], acc[mt][nb][3]);
            if (bias) {
                float2 bv = *(const float2*)(bias + col);
                v0.x += bv.x; v0.y += bv.y;
                v1.x += bv.x; v1.y += bv.y;
            }
            *(float2*)(C + (size_t)row * N + col)       = v0;
            *(float2*)(C + (size_t)(row + 8) * N + col) = v1;
        }
    }
}

// ---------------------------------------------------------------------------
// Tensor-core causal flash attention, bf16-split on QK and PV, fp32 softmax.
// BQ=128 (8 warps x 16 rows), BK=64. Per (b,h) head.
// smem tiles (padded strides): Qh/Ql [128 x 128]d, Kh/Kl [64 x 128]d,
// Vh/Vl transposed [128 d x 64 key].
// ---------------------------------------------------------------------------
#define AQSTR  272                 // Q/K row stride bytes (128 bf16 + 8 pad)
#define AVSTR  144                 // Vt row stride bytes (64 bf16 + 8 pad)
#define OFF_QH 0
#define OFF_QL (OFF_QH + 128 * AQSTR)          // 34816
#define OFF_KH (OFF_QL + 128 * AQSTR)          // 69632
#define OFF_KL (OFF_KH + 64 * AQSTR)           // 87040
#define OFF_VH (OFF_KL + 64 * AQSTR)           // 104448
#define OFF_VL (OFF_VH + 128 * AVSTR)          // 122880
#define ATTN_SMEM_B (OFF_VL + 128 * AVSTR)     // 141312

__global__ __launch_bounds__(256, 1)
void attn_mma_kernel(const float* __restrict__ qkv, float* __restrict__ out)
{
    extern __shared__ char smx[];
    const uint32_t sb = smem_u32(smx);

    const int t = threadIdx.x, w = t >> 5, lane = t & 31;
    const int qtile = (int)gridDim.x - 1 - (int)blockIdx.x;   // heavy tiles first
    const int bh = blockIdx.y;
    const int b = bh >> 4, h = bh & 15;
    const int qt0 = qtile * 128;
    const int wm = w * 16;
    const float scale = 0.08838834764831843f;   // 1/sqrt(128)

    // ---- load Q tile (scaled, split) ----
    {
        const int row = t >> 1, d0 = (t & 1) * 64;
        const float* gq = qkv + (size_t)(b * S_LEN + qt0 + row) * D3 + h * DH + d0;
        char* qh = smx + OFF_QH + row * AQSTR + d0 * 2;
        char* ql = smx + OFF_QL + row * AQSTR + d0 * 2;
#pragma unroll
        for (int f = 0; f < 16; ++f) {
            float4 v = *(const float4*)(gq + f * 4);
            uint32_t h0, l0, h1, l1;
            split2(v.x * scale, v.y * scale, h0, l0);
            split2(v.z * scale, v.w * scale, h1, l1);
            *(uint2*)(qh + f * 8) = make_uint2(h0, h1);
            *(uint2*)(ql + f * 8) = make_uint2(l0, l1);
        }
    }

    // ldmatrix bases
    const uint32_t qbh = sb + OFF_QH + (uint32_t)(wm + (lane & 15)) * AQSTR + (lane >> 4) * 16;
    const uint32_t qbl = qbh + (OFF_QL - OFF_QH);
    const uint32_t kbh = sb + OFF_KH + (uint32_t)(lane & 15) * AQSTR + (lane >> 4) * 16;
    const uint32_t kbl = kbh + (OFF_KL - OFF_KH);
    const uint32_t vbh = sb + OFF_VH + (uint32_t)(lane & 15) * AVSTR + (lane >> 4) * 16;
    const uint32_t vbl = vbh + (OFF_VL - OFF_VH);

    // state
    float o[16][4];
#pragma unroll
    for (int nb = 0; nb < 16; ++nb)
#pragma unroll
        for (int e = 0; e < 4; ++e) o[nb][e] = 0.f;
    float m_a = -1e30f, m_b = -1e30f, l_a = 0.f, l_b = 0.f;

    const int row_a = qt0 + wm + (lane >> 2);
    const int row_b = row_a + 8;

    const int nkt = (qt0 + 128) / 64;
    for (int kt = 0; kt < nkt; ++kt) {
        __syncthreads();   // previous tile's compute done with K/V smem
        // ---- load K (split) and V (split + transpose) ----
        {
            const int j = t >> 2, d0 = (t & 3) * 32;
            const float* gk = qkv + (size_t)(b * S_LEN + kt * 64 + j) * D3 + D_OUT + h * DH + d0;
            const float* gv = gk + D_OUT;
            char* kh = smx + OFF_KH + j * AQSTR + d0 * 2;
            char* kl = smx + OFF_KL + j * AQSTR + d0 * 2;
#pragma unroll
            for (int f = 0; f < 8; ++f) {
                float4 kv = *(const float4*)(gk + f * 4);
                uint32_t h0, l0, h1, l1;
                split2(kv.x, kv.y, h0, l0);
                split2(kv.z, kv.w, h1, l1);
                *(uint2*)(kh + f * 8) = make_uint2(h0, h1);
                *(uint2*)(kl + f * 8) = make_uint2(l0, l1);

                float4 vv = *(const float4*)(gv + f * 4);
                const int d = d0 + f * 4;
                __nv_bfloat16* vh = (__nv_bfloat16*)(smx + OFF_VH + d * AVSTR + j * 2);
                __nv_bfloat16* vl = (__nv_bfloat16*)(smx + OFF_VL + d * AVSTR + j * 2);
                float e[4] = {vv.x, vv.y, vv.z, vv.w};
#pragma unroll
                for (int q = 0; q < 4; ++q) {
                    __nv_bfloat16 hb = __float2bfloat16(e[q]);
                    *(__nv_bfloat16*)((char*)vh + q * AVSTR) = hb;
                    *(__nv_bfloat16*)((char*)vl + q * AVSTR) =
                        __float2bfloat16(e[q] - __bfloat162float(hb));
                }
            }
        }
        __syncthreads();

        // causal skip: warp inactive if all its rows are above the key tile
        if (kt * 64 > qt0 + wm + 15) continue;

        // ---- scores: S = Q K^T (3-term split) ----
        float sacc[8][4];
#pragma unroll
        for (int nb = 0; nb < 8; ++nb)
#pragma unroll
            for (int e = 0; e < 4; ++e) sacc[nb][e] = 0.f;

#pragma unroll
        for (int ks = 0; ks < 8; ++ks) {
            uint32_t ah[4], al[4];
            ldsm4(ah, qbh + ks * 32);
            ldsm4(al, qbl + ks * 32);
#pragma unroll
            for (int pg = 0; pg < 4; ++pg) {
                uint32_t bhh[4], bll[4];
                ldsm4(bhh, kbh + pg * 16 * AQSTR + ks * 32);
                ldsm4(bll, kbl + pg * 16 * AQSTR + ks * 32);
                mma_bf16(sacc[pg * 2],     ah, bhh[0], bhh[2]);
                mma_bf16(sacc[pg * 2],     ah, bll[0], bll[2]);
                mma_bf16(sacc[pg * 2],     al, bhh[0], bhh[2]);
                mma_bf16(sacc[pg * 2 + 1], ah, bhh[1], bhh[3]);
                mma_bf16(sacc[pg * 2 + 1], ah, bll[1], bll[3]);
                mma_bf16(sacc[pg * 2 + 1], al, bhh[1], bhh[3]);
            }
        }

        // ---- causal mask (only when tile straddles the diagonal) ----
        if (kt * 64 + 63 > qt0 + wm) {
#pragma unroll
            for (int nb = 0; nb < 8; ++nb) {
                const int col = kt * 64 + nb * 8 + (lane & 3) * 2;
                if (col > row_a)     sacc[nb][0] = -1e30f;
                if (col + 1 > row_a) sacc[nb][1] = -1e30f;
                if (col > row_b)     sacc[nb][2] = -1e30f;
                if (col + 1 > row_b) sacc[nb][3] = -1e30f;
            }
        }

        // ---- online softmax ----
        float mx_a = -1e30f, mx_b = -1e30f;
#pragma unroll
        for (int nb = 0; nb < 8; ++nb) {
            mx_a = fmaxf(mx_a, fmaxf(sacc[nb][0], sacc[nb][1]));
            mx_b = fmaxf(mx_b, fmaxf(sacc[nb][2], sacc[nb][3]));
        }
        mx_a = fmaxf(mx_a, __shfl_xor_sync(0xffffffffu, mx_a, 1));
        mx_a = fmaxf(mx_a, __shfl_xor_sync(0xffffffffu, mx_a, 2));
        mx_b = fmaxf(mx_b, __shfl_xor_sync(0xffffffffu, mx_b, 1));
        mx_b = fmaxf(mx_b, __shfl_xor_sync(0xffffffffu, mx_b, 2));

        const float mn_a = fmaxf(m_a, mx_a);
        const float mn_b = fmaxf(m_b, mx_b);
        const float al_a = __expf(m_a - mn_a);
        const float al_b = __expf(m_b - mn_b);
        m_a = mn_a; m_b = mn_b;

        float sum_a = 0.f, sum_b = 0.f;
#pragma unroll
        for (int nb = 0; nb < 8; ++nb) {
            sacc[nb][0] = __expf(sacc[nb][0] - mn_a);
            sacc[nb][1] = __expf(sacc[nb][1] - mn_a);
            sacc[nb][2] = __expf(sacc[nb][2] - mn_b);
            sacc[nb][3] = __expf(sacc[nb][3] - mn_b);
            sum_a += sacc[nb][0] + sacc[nb][1];
            sum_b += sacc[nb][2] + sacc[nb][3];
        }
        sum_a += __shfl_xor_sync(0xffffffffu, sum_a, 1);
        sum_a += __shfl_xor_sync(0xffffffffu, sum_a, 2);
        sum_b += __shfl_xor_sync(0xffffffffu, sum_b, 1);
        sum_b += __shfl_xor_sync(0xffffffffu, sum_b, 2);
        l_a = l_a * al_a + sum_a;
        l_b = l_b * al_b + sum_b;

#pragma unroll
        for (int nb = 0; nb < 16; ++nb) {
            o[nb][0] *= al_a; o[nb][1] *= al_a;
            o[nb][2] *= al_b; o[nb][3] *= al_b;
        }

        // ---- P fragments (C-layout == A-layout) + PV (3-term split) ----
#pragma unroll
        for (int kc = 0; kc < 4; ++kc) {
            uint32_t ph[4], pl[4];
            split2(sacc[2 * kc][0],     sacc[2 * kc][1],     ph[0], pl[0]);
            split2(sacc[2 * kc][2],     sacc[2 * kc][3],     ph[1], pl[1]);
            split2(sacc[2 * kc + 1][0], sacc[2 * kc + 1][1], ph[2], pl[2]);
            split2(sacc[2 * kc + 1][2], sacc[2 * kc + 1][3], ph[3], pl[3]);
#pragma unroll
            for (int pg = 0; pg < 8; ++pg) {
                uint32_t vh[4], vl[4];
                ldsm4(vh, vbh + pg * 16 * AVSTR + kc * 32);
                ldsm4(vl, vbl + pg * 16 * AVSTR + kc * 32);
                mma_bf16(o[pg * 2],     ph, vh[0], vh[2]);
                mma_bf16(o[pg * 2],     ph, vl[0], vl[2]);
                mma_bf16(o[pg * 2],     pl, vh[0], vh[2]);
                mma_bf16(o[pg * 2 + 1], ph, vh[1], vh[3]);
                mma_bf16(o[pg * 2 + 1], ph, vl[1], vl[3]);
                mma_bf16(o[pg * 2 + 1], pl, vh[1], vh[3]);
            }
        }
    }

    // ---- epilogue ----
    const float inv_a = 1.f / l_a;
    const float inv_b = 1.f / l_b;
    float* oa = out + (size_t)(b * S_LEN + row_a) * D_OUT + h * DH;
    float* ob = out + (size_t)(b * S_LEN + row_b) * D_OUT + h * DH;
#pragma unroll
    for (int nb = 0; nb < 16; ++nb) {
        const int col = nb * 8 + (lane & 3) * 2;
        *(float2*)(oa + col) = make_float2(o[nb][0] * inv_a, o[nb][1] * inv_a);
        *(float2*)(ob + col) = make_float2(o[nb][2] * inv_b, o[nb][3] * inv_b);
    }
}

// ---------------------------------------------------------------------------
// Launch
// ---------------------------------------------------------------------------
extern "C" void kernel_launch(void* const* d_in, const int* in_sizes, int n_in,
                              void* d_out, int out_size)
{
    const float* x      = (const float*)d_in[0];
    const float* w_qkv  = (const float*)d_in[1];
    const float* w_proj = (const float*)d_in[2];
    const float* b_proj = (const float*)d_in[3];
    float* out = (float*)d_out;

    void* qkvp = nullptr; void* attnp = nullptr;
    cudaGetSymbolAddress(&qkvp, g_qkv);
    cudaGetSymbolAddress(&attnp, g_attn);
    float* qkv  = (float*)qkvp;
    float* attn = (float*)attnp;

    cudaFuncSetAttribute(attn_mma_kernel,
                         cudaFuncAttributeMaxDynamicSharedMemorySize, ATTN_SMEM_B);

    // 1) QKV projection
    mma_gemm<<<dim3(D3 / 128, M_TOK / 128), 256>>>(x, w_qkv, nullptr, qkv,
                                                   M_TOK, D3, D_IN);
    // 2) Fused causal attention (tensor cores)
    attn_mma_kernel<<<dim3(S_LEN / 128, B_SZ * NHEAD), 256, ATTN_SMEM_B>>>(qkv, attn);
    // 3) Output projection + bias
    mma_gemm<<<dim3(D_OUT / 128, M_TOK / 128), 256>>>(attn, w_proj, b_proj, out,
                                                      M_TOK, D_OUT, D_OUT);
}

// round 5
// speedup vs baseline: 2.6879x; 1.2009x over previous
#include <cuda_runtime.h>
#include <cuda_bf16.h>
#include <math.h>
#include <stdint.h>

// ---------------------------------------------------------------------------
// Problem constants
// ---------------------------------------------------------------------------
#define B_SZ    2
#define S_LEN   2048
#define D_IN    2048
#define D_OUT   2048
#define NHEAD   16
#define DH      128
#define D3      6144
#define M_TOK   (B_SZ * S_LEN)

// Scratch (bf16 hi/lo split operands)
__device__ __nv_bfloat16 g_xh[(size_t)M_TOK * D_IN];
__device__ __nv_bfloat16 g_xl[(size_t)M_TOK * D_IN];
__device__ __nv_bfloat16 g_wqh[(size_t)D3 * D_IN];
__device__ __nv_bfloat16 g_wql[(size_t)D3 * D_IN];
__device__ __nv_bfloat16 g_wph[(size_t)D_OUT * D_OUT];
__device__ __nv_bfloat16 g_wpl[(size_t)D_OUT * D_OUT];
__device__ __nv_bfloat16 g_qkvh[(size_t)M_TOK * D3];
__device__ __nv_bfloat16 g_qkvl[(size_t)M_TOK * D3];
__device__ __nv_bfloat16 g_ah[(size_t)M_TOK * D_OUT];
__device__ __nv_bfloat16 g_al[(size_t)M_TOK * D_OUT];

// ---------------------------------------------------------------------------
// Helpers
// ---------------------------------------------------------------------------
__device__ __forceinline__ uint32_t smem_u32(const void* p) {
    uint32_t a;
    asm("{ .reg .u64 t; cvta.to.shared.u64 t, %1; cvt.u32.u64 %0, t; }" : "=r"(a) : "l"(p));
    return a;
}

__device__ __forceinline__ void split2(float x, float y, uint32_t& hi, uint32_t& lo) {
    __nv_bfloat16 hx = __float2bfloat16(x);
    __nv_bfloat16 hy = __float2bfloat16(y);
    float rx = x - __bfloat162float(hx);
    float ry = y - __bfloat162float(hy);
    __nv_bfloat162 h2 = __halves2bfloat162(hx, hy);
    __nv_bfloat162 l2 = __halves2bfloat162(__float2bfloat16(rx), __float2bfloat16(ry));
    hi = *reinterpret_cast<uint32_t*>(&h2);
    lo = *reinterpret_cast<uint32_t*>(&l2);
}

__device__ __forceinline__ void ldsm4(uint32_t* r, uint32_t addr) {
    asm volatile("ldmatrix.sync.aligned.m8n8.x4.shared.b16 {%0,%1,%2,%3}, [%4];"
                 : "=r"(r[0]), "=r"(r[1]), "=r"(r[2]), "=r"(r[3]) : "r"(addr));
}
__device__ __forceinline__ void ldsm4t(uint32_t* r, uint32_t addr) {
    asm volatile("ldmatrix.sync.aligned.m8n8.x4.trans.shared.b16 {%0,%1,%2,%3}, [%4];"
                 : "=r"(r[0]), "=r"(r[1]), "=r"(r[2]), "=r"(r[3]) : "r"(addr));
}
__device__ __forceinline__ void mma_bf16(float* c, const uint32_t* a, uint32_t b0, uint32_t b1) {
    asm volatile(
        "mma.sync.aligned.m16n8k16.row.col.f32.bf16.bf16.f32 "
        "{%0,%1,%2,%3}, {%4,%5,%6,%7}, {%8,%9}, {%0,%1,%2,%3};"
        : "+f"(c[0]), "+f"(c[1]), "+f"(c[2]), "+f"(c[3])
        : "r"(a[0]), "r"(a[1]), "r"(a[2]), "r"(a[3]), "r"(b0), "r"(b1));
}
__device__ __forceinline__ void cp16(uint32_t dst, const void* src) {
    asm volatile("cp.async.cg.shared.global [%0], [%1], 16;" :: "r"(dst), "l"(src));
}
#define CP_COMMIT() asm volatile("cp.async.commit_group;" ::: "memory")
#define CP_WAIT(n)  asm volatile("cp.async.wait_group %0;" :: "n"(n) : "memory")

// ---------------------------------------------------------------------------
// Split kernel: f32 -> bf16 hi/lo
// ---------------------------------------------------------------------------
__global__ void split_f32(const float4* __restrict__ in, uint2* __restrict__ hi,
                          uint2* __restrict__ lo, int n4)
{
    int i = blockIdx.x * blockDim.x + threadIdx.x;
    if (i >= n4) return;
    float4 v = in[i];
    uint32_t h0, l0, h1, l1;
    split2(v.x, v.y, h0, l0);
    split2(v.z, v.w, h1, l1);
    hi[i] = make_uint2(h0, h1);
    lo[i] = make_uint2(l0, l1);
}

// ---------------------------------------------------------------------------
// bf16-split tensor-core GEMM: C = A @ B^T, operands pre-split bf16 in gmem.
// 128x128 tile, BK=32, cp.async double-buffered, 8 warps (4m x 2n).
// Output: either f32 (+bias) or split bf16 hi/lo.
// ---------------------------------------------------------------------------
#define GBK     32
#define ROWB    80                     // 32 bf16 + 8 pad = 80 bytes
#define TILE_BY (128 * ROWB)           // 10240
#define STAGE_BY (4 * TILE_BY)         // 40960
#define GEMM_SMEM (2 * STAGE_BY)       // 81920

__global__ __launch_bounds__(256, 2)
void mma_gemm(const __nv_bfloat16* __restrict__ Ah, const __nv_bfloat16* __restrict__ Al,
              const __nv_bfloat16* __restrict__ Bh, const __nv_bfloat16* __restrict__ Bl,
              const float* __restrict__ bias, float* __restrict__ C,
              __nv_bfloat16* __restrict__ Ch, __nv_bfloat16* __restrict__ Cl,
              int M, int N, int K)
{
    extern __shared__ char smem[];
    const uint32_t sb = smem_u32(smem);

    const int tid  = threadIdx.x;
    const int wid  = tid >> 5, lane = tid & 31;
    const int m0   = blockIdx.y << 7;
    const int n0   = blockIdx.x << 7;
    const int wm   = (wid & 3) * 32;
    const int wn   = (wid >> 2) * 64;

    const __nv_bfloat16* base0 = Ah + (size_t)m0 * K;
    const __nv_bfloat16* base1 = Al + (size_t)m0 * K;
    const __nv_bfloat16* base2 = Bh + (size_t)n0 * K;
    const __nv_bfloat16* base3 = Bl + (size_t)n0 * K;

    const uint32_t aoff = (uint32_t)(wm + (lane & 15)) * ROWB + (lane >> 4) * 16;
    const uint32_t boff = (uint32_t)(wn + (lane & 15)) * ROWB + (lane >> 4) * 16;

    float acc[2][8][4];
#pragma unroll
    for (int mt = 0; mt < 2; ++mt)
#pragma unroll
        for (int nb = 0; nb < 8; ++nb)
#pragma unroll
            for (int e = 0; e < 4; ++e) acc[mt][nb][e] = 0.f;

    auto load_chunk = [&](int stage, int k0) {
        const uint32_t sbase = sb + stage * STAGE_BY;
        const int seg = tid & 3;
        const int r0 = tid >> 2;
#pragma unroll
        for (int i = 0; i < 8; ++i) {
            const int tile = i >> 1;
            const int row = (i & 1) * 64 + r0;
            const __nv_bfloat16* bp = (tile == 0) ? base0 : (tile == 1) ? base1
                                     : (tile == 2) ? base2 : base3;
            cp16(sbase + tile * TILE_BY + row * ROWB + seg * 16,
                 bp + (size_t)row * K + k0 + seg * 8);
        }
    };

    const int nchunk = K / GBK;
    load_chunk(0, 0);
    CP_COMMIT();

    for (int i = 0; i < nchunk; ++i) {
        if (i + 1 < nchunk) {
            load_chunk((i + 1) & 1, (i + 1) * GBK);
            CP_COMMIT();
            CP_WAIT(1);
        } else {
            CP_WAIT(0);
        }
        __syncthreads();

        const uint32_t st = sb + (i & 1) * STAGE_BY;
        const uint32_t sAh = st, sAl = st + TILE_BY, sBh = st + 2 * TILE_BY, sBl = st + 3 * TILE_BY;
#pragma unroll
        for (int ks = 0; ks < 2; ++ks) {
            uint32_t ah[2][4], al[2][4];
#pragma unroll
            for (int mt = 0; mt < 2; ++mt) {
                ldsm4(ah[mt], sAh + aoff + mt * 16 * ROWB + ks * 32);
                ldsm4(al[mt], sAl + aoff + mt * 16 * ROWB + ks * 32);
            }
#pragma unroll
            for (int pg = 0; pg < 4; ++pg) {
                uint32_t bh[4], bl[4];
                ldsm4(bh, sBh + boff + pg * 16 * ROWB + ks * 32);
                ldsm4(bl, sBl + boff + pg * 16 * ROWB + ks * 32);
#pragma unroll
                for (int mt = 0; mt < 2; ++mt) {
                    mma_bf16(acc[mt][pg * 2],     ah[mt], bh[0], bh[2]);
                    mma_bf16(acc[mt][pg * 2],     ah[mt], bl[0], bl[2]);
                    mma_bf16(acc[mt][pg * 2],     al[mt], bh[0], bh[2]);
                    mma_bf16(acc[mt][pg * 2 + 1], ah[mt], bh[1], bh[3]);
                    mma_bf16(acc[mt][pg * 2 + 1], ah[mt], bl[1], bl[3]);
                    mma_bf16(acc[mt][pg * 2 + 1], al[mt], bh[1], bh[3]);
                }
            }
        }
        __syncthreads();
    }

    const int crow = lane >> 2;
    const int ccol = (lane & 3) * 2;
    if (C) {
        // f32 output (+bias)
#pragma unroll
        for (int mt = 0; mt < 2; ++mt)
#pragma unroll
            for (int nb = 0; nb < 8; ++nb) {
                const int row = m0 + wm + mt * 16 + crow;
                const int col = n0 + wn + nb * 8 + ccol;
                float2 v0 = make_float2(acc[mt][nb][0], acc[mt][nb][1]);
                float2 v1 = make_float2(acc[mt][nb][2], acc[mt][nb][3]);
                if (bias) {
                    float2 bv = *(const float2*)(bias + col);
                    v0.x += bv.x; v0.y += bv.y;
                    v1.x += bv.x; v1.y += bv.y;
                }
                *(float2*)(C + (size_t)row * N + col)       = v0;
                *(float2*)(C + (size_t)(row + 8) * N + col) = v1;
            }
    } else {
        // split bf16 output
#pragma unroll
        for (int mt = 0; mt < 2; ++mt)
#pragma unroll
            for (int nb = 0; nb < 8; ++nb) {
                const int row = m0 + wm + mt * 16 + crow;
                const int col = n0 + wn + nb * 8 + ccol;
                uint32_t h0, l0, h1, l1;
                split2(acc[mt][nb][0], acc[mt][nb][1], h0, l0);
                split2(acc[mt][nb][2], acc[mt][nb][3], h1, l1);
                *(uint32_t*)(Ch + (size_t)row * N + col)       = h0;
                *(uint32_t*)(Cl + (size_t)row * N + col)       = l0;
                *(uint32_t*)(Ch + (size_t)(row + 8) * N + col) = h1;
                *(uint32_t*)(Cl + (size_t)(row + 8) * N + col) = l1;
            }
    }
}

// ---------------------------------------------------------------------------
// Tensor-core causal flash attention. Operands pre-split bf16 (from QKV GEMM).
// BQ=128 (8 warps x 16 rows), BK=64, K/V double-buffered via cp.async.
// V kept row-major; B-fragments via ldmatrix.trans. Output split bf16.
// ---------------------------------------------------------------------------
#define ASTR    272                    // row stride bytes (128 bf16 + 8 pad)
#define QTILE_B (128 * ASTR)           // 34816
#define KVTILE  (64 * ASTR)            // 17408
#define KVSTAGE (4 * KVTILE)           // 69632
#define OFF_KV  (2 * QTILE_B)          // Q hi+lo first
#define ATTN_SMEM_B (OFF_KV + 2 * KVSTAGE)   // 208896

__global__ __launch_bounds__(256, 1)
void attn_mma(const __nv_bfloat16* __restrict__ qh, const __nv_bfloat16* __restrict__ ql,
              __nv_bfloat16* __restrict__ oh, __nv_bfloat16* __restrict__ ol)
{
    extern __shared__ char smx[];
    const uint32_t sb = smem_u32(smx);

    const int t = threadIdx.x, w = t >> 5, lane = t & 31;
    const int qtile = (int)gridDim.x - 1 - (int)blockIdx.x;
    const int bh = blockIdx.y;
    const int b = bh >> 4, h = bh & 15;
    const int qt0 = qtile * 128;
    const int wm = w * 16;
    const float scale = 0.08838834764831843f;

    // ---- issue Q (hi+lo) ----
    {
        const int seg = t & 15, r0 = t >> 4;
#pragma unroll
        for (int i = 0; i < 16; ++i) {
            const int tile = i >> 3;               // 0=hi, 1=lo
            const int row = (i & 7) * 16 + r0;
            const __nv_bfloat16* src = (tile ? ql : qh)
                + (size_t)(b * S_LEN + qt0 + row) * D3 + h * DH + seg * 8;
            cp16(sb + tile * QTILE_B + row * ASTR + seg * 16, src);
        }
    }

    auto kv_load = [&](int kt, int s) {
        const int seg = t & 15, r0 = t >> 4;
        const uint32_t sbase = sb + OFF_KV + s * KVSTAGE;
#pragma unroll
        for (int i = 0; i < 16; ++i) {
            const int tile = i >> 2;               // 0=Kh 1=Kl 2=Vh 3=Vl
            const int row = (i & 3) * 16 + r0;
            const __nv_bfloat16* src = ((tile & 1) ? ql : qh)
                + (size_t)(b * S_LEN + kt * 64 + row) * D3
                + D_OUT + (tile >> 1) * D_OUT + h * DH + seg * 8;
            cp16(sbase + (tile >> 1) * (2 * KVTILE) + (tile & 1) * KVTILE
                 + row * ASTR + seg * 16, src);
        }
    };

    kv_load(0, 0);
    CP_COMMIT();

    // ldmatrix lane components
    const uint32_t qbh = sb + (uint32_t)(wm + (lane & 15)) * ASTR + (lane >> 4) * 16;
    const uint32_t qbl = qbh + QTILE_B;
    const uint32_t klo = (uint32_t)(lane & 15) * ASTR + (lane >> 4) * 16;
    const uint32_t vlo = (uint32_t)(((lane >> 4) << 3) + (lane & 7)) * ASTR
                         + ((lane >> 3) & 1) * 16;

    float o[16][4];
#pragma unroll
    for (int nb = 0; nb < 16; ++nb)
#pragma unroll
        for (int e = 0; e < 4; ++e) o[nb][e] = 0.f;
    float m_a = -1e30f, m_b = -1e30f, l_a = 0.f, l_b = 0.f;

    const int row_a = qt0 + wm + (lane >> 2);
    const int row_b = row_a + 8;

    const int nkt = (qt0 + 128) / 64;
    for (int kt = 0; kt < nkt; ++kt) {
        if (kt + 1 < nkt) {
            kv_load(kt + 1, (kt + 1) & 1);
            CP_COMMIT();
            CP_WAIT(1);
        } else {
            CP_WAIT(0);
        }
        __syncthreads();

        if (kt * 64 <= qt0 + wm + 15) {
            const uint32_t stb = sb + OFF_KV + (kt & 1) * KVSTAGE;
            const uint32_t kbh = stb + klo;
            const uint32_t kbl = kbh + KVTILE;
            const uint32_t vbh = stb + 2 * KVTILE + vlo;
            const uint32_t vbl = vbh + KVTILE;

            // ---- scores ----
            float sacc[8][4];
#pragma unroll
            for (int nb = 0; nb < 8; ++nb)
#pragma unroll
                for (int e = 0; e < 4; ++e) sacc[nb][e] = 0.f;

#pragma unroll
            for (int ks = 0; ks < 8; ++ks) {
                uint32_t ah[4], al[4];
                ldsm4(ah, qbh + ks * 32);
                ldsm4(al, qbl + ks * 32);
#pragma unroll
                for (int pg = 0; pg < 4; ++pg) {
                    uint32_t bhh[4], bll[4];
                    ldsm4(bhh, kbh + pg * 16 * ASTR + ks * 32);
                    ldsm4(bll, kbl + pg * 16 * ASTR + ks * 32);
                    mma_bf16(sacc[pg * 2],     ah, bhh[0], bhh[2]);
                    mma_bf16(sacc[pg * 2],     ah, bll[0], bll[2]);
                    mma_bf16(sacc[pg * 2],     al, bhh[0], bhh[2]);
                    mma_bf16(sacc[pg * 2 + 1], ah, bhh[1], bhh[3]);
                    mma_bf16(sacc[pg * 2 + 1], ah, bll[1], bll[3]);
                    mma_bf16(sacc[pg * 2 + 1], al, bhh[1], bhh[3]);
                }
            }
#pragma unroll
            for (int nb = 0; nb < 8; ++nb)
#pragma unroll
                for (int e = 0; e < 4; ++e) sacc[nb][e] *= scale;

            // ---- causal mask ----
            if (kt * 64 + 63 > qt0 + wm) {
#pragma unroll
                for (int nb = 0; nb < 8; ++nb) {
                    const int col = kt * 64 + nb * 8 + (lane & 3) * 2;
                    if (col > row_a)     sacc[nb][0] = -1e30f;
                    if (col + 1 > row_a) sacc[nb][1] = -1e30f;
                    if (col > row_b)     sacc[nb][2] = -1e30f;
                    if (col + 1 > row_b) sacc[nb][3] = -1e30f;
                }
            }

            // ---- online softmax ----
            float mx_a = -1e30f, mx_b = -1e30f;
#pragma unroll
            for (int nb = 0; nb < 8; ++nb) {
                mx_a = fmaxf(mx_a, fmaxf(sacc[nb][0], sacc[nb][1]));
                mx_b = fmaxf(mx_b, fmaxf(sacc[nb][2], sacc[nb][3]));
            }
            mx_a = fmaxf(mx_a, __shfl_xor_sync(0xffffffffu, mx_a, 1));
            mx_a = fmaxf(mx_a, __shfl_xor_sync(0xffffffffu, mx_a, 2));
            mx_b = fmaxf(mx_b, __shfl_xor_sync(0xffffffffu, mx_b, 1));
            mx_b = fmaxf(mx_b, __shfl_xor_sync(0xffffffffu, mx_b, 2));

            const float mn_a = fmaxf(m_a, mx_a);
            const float mn_b = fmaxf(m_b, mx_b);
            const float al_a = __expf(m_a - mn_a);
            const float al_b = __expf(m_b - mn_b);
            m_a = mn_a; m_b = mn_b;

            float sum_a = 0.f, sum_b = 0.f;
#pragma unroll
            for (int nb = 0; nb < 8; ++nb) {
                sacc[nb][0] = __expf(sacc[nb][0] - mn_a);
                sacc[nb][1] = __expf(sacc[nb][1] - mn_a);
                sacc[nb][2] = __expf(sacc[nb][2] - mn_b);
                sacc[nb][3] = __expf(sacc[nb][3] - mn_b);
                sum_a += sacc[nb][0] + sacc[nb][1];
                sum_b += sacc[nb][2] + sacc[nb][3];
            }
            sum_a += __shfl_xor_sync(0xffffffffu, sum_a, 1);
            sum_a += __shfl_xor_sync(0xffffffffu, sum_a, 2);
            sum_b += __shfl_xor_sync(0xffffffffu, sum_b, 1);
            sum_b += __shfl_xor_sync(0xffffffffu, sum_b, 2);
            l_a = l_a * al_a + sum_a;
            l_b = l_b * al_b + sum_b;

#pragma unroll
            for (int nb = 0; nb < 16; ++nb) {
                o[nb][0] *= al_a; o[nb][1] *= al_a;
                o[nb][2] *= al_b; o[nb][3] *= al_b;
            }

            // ---- PV (P from accumulator layout; V via ldmatrix.trans) ----
#pragma unroll
            for (int kc = 0; kc < 4; ++kc) {
                uint32_t ph[4], pl[4];
                split2(sacc[2 * kc][0],     sacc[2 * kc][1],     ph[0], pl[0]);
                split2(sacc[2 * kc][2],     sacc[2 * kc][3],     ph[1], pl[1]);
                split2(sacc[2 * kc + 1][0], sacc[2 * kc + 1][1], ph[2], pl[2]);
                split2(sacc[2 * kc + 1][2], sacc[2 * kc + 1][3], ph[3], pl[3]);
#pragma unroll
                for (int pg = 0; pg < 8; ++pg) {
                    uint32_t vh[4], vl[4];
                    ldsm4t(vh, vbh + kc * 16 * ASTR + pg * 32);
                    ldsm4t(vl, vbl + kc * 16 * ASTR + pg * 32);
                    mma_bf16(o[pg * 2],     ph, vh[0], vh[2]);
                    mma_bf16(o[pg * 2],     ph, vl[0], vl[2]);
                    mma_bf16(o[pg * 2],     pl, vh[0], vh[2]);
                    mma_bf16(o[pg * 2 + 1], ph, vh[1], vh[3]);
                    mma_bf16(o[pg * 2 + 1], ph, vl[1], vl[3]);
                    mma_bf16(o[pg * 2 + 1], pl, vh[1], vh[3]);
                }
            }
        }
        __syncthreads();
    }

    // ---- epilogue: split bf16 output ----
    const float inv_a = 1.f / l_a;
    const float inv_b = 1.f / l_b;
    const size_t oa = (size_t)(b * S_LEN + row_a) * D_OUT + h * DH;
    const size_t ob = (size_t)(b * S_LEN + row_b) * D_OUT + h * DH;
#pragma unroll
    for (int nb = 0; nb < 16; ++nb) {
        const int col = nb * 8 + (lane & 3) * 2;
        uint32_t h0, l0, h1, l1;
        split2(o[nb][0] * inv_a, o[nb][1] * inv_a, h0, l0);
        split2(o[nb][2] * inv_b, o[nb][3] * inv_b, h1, l1);
        *(uint32_t*)(oh + oa + col) = h0;
        *(uint32_t*)(ol + oa + col) = l0;
        *(uint32_t*)(oh + ob + col) = h1;
        *(uint32_t*)(ol + ob + col) = l1;
    }
}

// ---------------------------------------------------------------------------
// Launch
// ---------------------------------------------------------------------------
extern "C" void kernel_launch(void* const* d_in, const int* in_sizes, int n_in,
                              void* d_out, int out_size)
{
    const float* x      = (const float*)d_in[0];
    const float* w_qkv  = (const float*)d_in[1];
    const float* w_proj = (const float*)d_in[2];
    const float* b_proj = (const float*)d_in[3];
    float* out = (float*)d_out;

    void *xh, *xl, *wqh, *wql, *wph, *wpl, *qkvh, *qkvl, *ah, *al;
    cudaGetSymbolAddress(&xh, g_xh);   cudaGetSymbolAddress(&xl, g_xl);
    cudaGetSymbolAddress(&wqh, g_wqh); cudaGetSymbolAddress(&wql, g_wql);
    cudaGetSymbolAddress(&wph, g_wph); cudaGetSymbolAddress(&wpl, g_wpl);
    cudaGetSymbolAddress(&qkvh, g_qkvh); cudaGetSymbolAddress(&qkvl, g_qkvl);
    cudaGetSymbolAddress(&ah, g_ah);   cudaGetSymbolAddress(&al, g_al);

    cudaFuncSetAttribute(mma_gemm, cudaFuncAttributeMaxDynamicSharedMemorySize, GEMM_SMEM);
    cudaFuncSetAttribute(attn_mma, cudaFuncAttributeMaxDynamicSharedMemorySize, ATTN_SMEM_B);

    // 0) pre-split inputs to bf16 hi/lo
    {
        int n4;
        n4 = M_TOK * D_IN / 4;
        split_f32<<<(n4 + 255) / 256, 256>>>((const float4*)x, (uint2*)xh, (uint2*)xl, n4);
        n4 = D3 * D_IN / 4;
        split_f32<<<(n4 + 255) / 256, 256>>>((const float4*)w_qkv, (uint2*)wqh, (uint2*)wql, n4);
        n4 = D_OUT * D_OUT / 4;
        split_f32<<<(n4 + 255) / 256, 256>>>((const float4*)w_proj, (uint2*)wph, (uint2*)wpl, n4);
    }

    // 1) QKV projection -> split bf16 qkv
    mma_gemm<<<dim3(D3 / 128, M_TOK / 128), 256, GEMM_SMEM>>>(
        (const __nv_bfloat16*)xh, (const __nv_bfloat16*)xl,
        (const __nv_bfloat16*)wqh, (const __nv_bfloat16*)wql,
        nullptr, nullptr, (__nv_bfloat16*)qkvh, (__nv_bfloat16*)qkvl,
        M_TOK, D3, D_IN);

    // 2) Fused causal attention -> split bf16
    attn_mma<<<dim3(S_LEN / 128, B_SZ * NHEAD), 256, ATTN_SMEM_B>>>(
        (const __nv_bfloat16*)qkvh, (const __nv_bfloat16*)qkvl,
        (__nv_bfloat16*)ah, (__nv_bfloat16*)al);

    // 3) Output projection + bias -> f32 out
    mma_gemm<<<dim3(D_OUT / 128, M_TOK / 128), 256, GEMM_SMEM>>>(
        (const __nv_bfloat16*)ah, (const __nv_bfloat16*)al,
        (const __nv_bfloat16*)wph, (const __nv_bfloat16*)wpl,
        b_proj, out, nullptr, nullptr,
        M_TOK, D_OUT, D_OUT);
}

// round 6
// speedup vs baseline: 4.2700x; 1.5886x over previous
#include <cuda_runtime.h>
#include <cuda_fp16.h>
#include <math.h>
#include <stdint.h>

// ---------------------------------------------------------------------------
// Problem constants
// ---------------------------------------------------------------------------
#define B_SZ    2
#define S_LEN   2048
#define D_IN    2048
#define D_OUT   2048
#define NHEAD   16
#define DH      128
#define D3      6144
#define M_TOK   (B_SZ * S_LEN)
#define QSCALE  0.08838834764831843f   // 1/sqrt(128)

// Scratch (fp16 operands; weights split hi/lo, activations single)
__device__ __half g_x16[(size_t)M_TOK * D_IN];
__device__ __half g_wqh[(size_t)D3 * D_IN];
__device__ __half g_wql[(size_t)D3 * D_IN];
__device__ __half g_wph[(size_t)D_OUT * D_OUT];
__device__ __half g_wpl[(size_t)D_OUT * D_OUT];
__device__ __half g_qkvh[(size_t)M_TOK * D3];
__device__ __half g_qkvl[(size_t)M_TOK * D3];   // lo only written for Q cols
__device__ __half g_a16[(size_t)M_TOK * D_OUT];

// ---------------------------------------------------------------------------
// Helpers
// ---------------------------------------------------------------------------
__device__ __forceinline__ uint32_t smem_u32(const void* p) {
    uint32_t a;
    asm("{ .reg .u64 t; cvta.to.shared.u64 t, %1; cvt.u32.u64 %0, t; }" : "=r"(a) : "l"(p));
    return a;
}
__device__ __forceinline__ uint32_t packh2(float x, float y) {
    __half2 h = __floats2half2_rn(x, y);
    return *reinterpret_cast<uint32_t*>(&h);
}
__device__ __forceinline__ void split2h(float x, float y, uint32_t& hi, uint32_t& lo) {
    __half hx = __float2half_rn(x), hy = __float2half_rn(y);
    float rx = x - __half2float(hx), ry = y - __half2float(hy);
    __half2 h2 = __halves2half2(hx, hy);
    __half2 l2 = __halves2half2(__float2half_rn(rx), __float2half_rn(ry));
    hi = *reinterpret_cast<uint32_t*>(&h2);
    lo = *reinterpret_cast<uint32_t*>(&l2);
}
__device__ __forceinline__ void ldsm4(uint32_t* r, uint32_t addr) {
    asm volatile("ldmatrix.sync.aligned.m8n8.x4.shared.b16 {%0,%1,%2,%3}, [%4];"
                 : "=r"(r[0]), "=r"(r[1]), "=r"(r[2]), "=r"(r[3]) : "r"(addr));
}
__device__ __forceinline__ void ldsm4t(uint32_t* r, uint32_t addr) {
    asm volatile("ldmatrix.sync.aligned.m8n8.x4.trans.shared.b16 {%0,%1,%2,%3}, [%4];"
                 : "=r"(r[0]), "=r"(r[1]), "=r"(r[2]), "=r"(r[3]) : "r"(addr));
}
__device__ __forceinline__ void mma_f16(float* c, const uint32_t* a, uint32_t b0, uint32_t b1) {
    asm volatile(
        "mma.sync.aligned.m16n8k16.row.col.f32.f16.f16.f32 "
        "{%0,%1,%2,%3}, {%4,%5,%6,%7}, {%8,%9}, {%0,%1,%2,%3};"
        : "+f"(c[0]), "+f"(c[1]), "+f"(c[2]), "+f"(c[3])
        : "r"(a[0]), "r"(a[1]), "r"(a[2]), "r"(a[3]), "r"(b0), "r"(b1));
}
__device__ __forceinline__ void cp16(uint32_t dst, const void* src) {
    asm volatile("cp.async.cg.shared.global [%0], [%1], 16;" :: "r"(dst), "l"(src));
}
#define CP_COMMIT() asm volatile("cp.async.commit_group;" ::: "memory")
#define CP_WAIT(n)  asm volatile("cp.async.wait_group %0;" :: "n"(n) : "memory")

// ---------------------------------------------------------------------------
// Conversion kernels
// ---------------------------------------------------------------------------
__global__ void tohalf_k(const float4* __restrict__ in, uint2* __restrict__ out, int n4)
{
    int i = blockIdx.x * blockDim.x + threadIdx.x;
    if (i >= n4) return;
    float4 v = in[i];
    out[i] = make_uint2(packh2(v.x, v.y), packh2(v.z, v.w));
}
__global__ void splith_k(const float4* __restrict__ in, uint2* __restrict__ hi,
                         uint2* __restrict__ lo, int n4)
{
    int i = blockIdx.x * blockDim.x + threadIdx.x;
    if (i >= n4) return;
    float4 v = in[i];
    uint32_t h0, l0, h1, l1;
    split2h(v.x, v.y, h0, l0);
    split2h(v.z, v.w, h1, l1);
    hi[i] = make_uint2(h0, h1);
    lo[i] = make_uint2(l0, l1);
}

// ---------------------------------------------------------------------------
// fp16 split tensor-core GEMM: C = A @ (Bh+Bl)^T.
// A single fp16, B split hi/lo. 128x128 tile, BK=32, cp.async double-buffered.
// Out: f32 (+bias) OR split fp16 (Q cols scaled by qscale, lo only for Q cols).
// ---------------------------------------------------------------------------
#define GBK      32
#define ROWB     80                    // 32 fp16 (64B) + 16B pad
#define TILE_BY  (128 * ROWB)          // 10240
#define STAGE_BY (3 * TILE_BY)         // 30720
#define GEMM_SMEM (2 * STAGE_BY)       // 61440

__global__ __launch_bounds__(256, 2)
void mma_gemm(const __half* __restrict__ A,
              const __half* __restrict__ Bh, const __half* __restrict__ Bl,
              const float* __restrict__ bias, float* __restrict__ C,
              __half* __restrict__ Ch, __half* __restrict__ Cl,
              int M, int N, int K, float qscale, int qcols)
{
    extern __shared__ char smem[];
    const uint32_t sb = smem_u32(smem);

    const int tid  = threadIdx.x;
    const int wid  = tid >> 5, lane = tid & 31;
    const int m0   = blockIdx.y << 7;
    const int n0   = blockIdx.x << 7;
    const int wm   = (wid & 3) * 32;
    const int wn   = (wid >> 2) * 64;

    const __half* baseA  = A  + (size_t)m0 * K;
    const __half* baseBh = Bh + (size_t)n0 * K;
    const __half* baseBl = Bl + (size_t)n0 * K;

    const uint32_t aoff = (uint32_t)(wm + (lane & 15)) * ROWB + (lane >> 4) * 16;
    const uint32_t boff = (uint32_t)(wn + (lane & 15)) * ROWB + (lane >> 4) * 16;

    float acc[2][8][4];
#pragma unroll
    for (int mt = 0; mt < 2; ++mt)
#pragma unroll
        for (int nb = 0; nb < 8; ++nb)
#pragma unroll
            for (int e = 0; e < 4; ++e) acc[mt][nb][e] = 0.f;

    auto load_chunk = [&](int stage, int k0) {
        const uint32_t sbase = sb + stage * STAGE_BY;
        const int seg = tid & 3;
        const int r0 = tid >> 2;
#pragma unroll
        for (int i = 0; i < 6; ++i) {
            const int tile = i >> 1;
            const int row = (i & 1) * 64 + r0;
            const __half* bp = (tile == 0) ? baseA : (tile == 1) ? baseBh : baseBl;
            cp16(sbase + tile * TILE_BY + row * ROWB + seg * 16,
                 bp + (size_t)row * K + k0 + seg * 8);
        }
    };

    const int nchunk = K / GBK;
    load_chunk(0, 0);
    CP_COMMIT();

    for (int i = 0; i < nchunk; ++i) {
        if (i + 1 < nchunk) {
            load_chunk((i + 1) & 1, (i + 1) * GBK);
            CP_COMMIT();
            CP_WAIT(1);
        } else {
            CP_WAIT(0);
        }
        __syncthreads();

        const uint32_t st = sb + (i & 1) * STAGE_BY;
        const uint32_t sA = st, sBh2 = st + TILE_BY, sBl2 = st + 2 * TILE_BY;
#pragma unroll
        for (int ks = 0; ks < 2; ++ks) {
            uint32_t a[2][4];
#pragma unroll
            for (int mt = 0; mt < 2; ++mt)
                ldsm4(a[mt], sA + aoff + mt * 16 * ROWB + ks * 32);
#pragma unroll
            for (int pg = 0; pg < 4; ++pg) {
                uint32_t bh[4], bl[4];
                ldsm4(bh, sBh2 + boff + pg * 16 * ROWB + ks * 32);
                ldsm4(bl, sBl2 + boff + pg * 16 * ROWB + ks * 32);
#pragma unroll
                for (int mt = 0; mt < 2; ++mt) {
                    mma_f16(acc[mt][pg * 2],     a[mt], bh[0], bh[2]);
                    mma_f16(acc[mt][pg * 2],     a[mt], bl[0], bl[2]);
                    mma_f16(acc[mt][pg * 2 + 1], a[mt], bh[1], bh[3]);
                    mma_f16(acc[mt][pg * 2 + 1], a[mt], bl[1], bl[3]);
                }
            }
        }
        __syncthreads();
    }

    const int crow = lane >> 2;
    const int ccol = (lane & 3) * 2;
    if (C) {
#pragma unroll
        for (int mt = 0; mt < 2; ++mt)
#pragma unroll
            for (int nb = 0; nb < 8; ++nb) {
                const int row = m0 + wm + mt * 16 + crow;
                const int col = n0 + wn + nb * 8 + ccol;
                float2 v0 = make_float2(acc[mt][nb][0], acc[mt][nb][1]);
                float2 v1 = make_float2(acc[mt][nb][2], acc[mt][nb][3]);
                if (bias) {
                    float2 bv = *(const float2*)(bias + col);
                    v0.x += bv.x; v0.y += bv.y;
                    v1.x += bv.x; v1.y += bv.y;
                }
                *(float2*)(C + (size_t)row * N + col)       = v0;
                *(float2*)(C + (size_t)(row + 8) * N + col) = v1;
            }
    } else {
#pragma unroll
        for (int mt = 0; mt < 2; ++mt)
#pragma unroll
            for (int nb = 0; nb < 8; ++nb) {
                const int row = m0 + wm + mt * 16 + crow;
                const int col = n0 + wn + nb * 8 + ccol;
                const bool isq = (col < qcols);
                const float s = isq ? qscale : 1.f;
                uint32_t h0, l0, h1, l1;
                split2h(acc[mt][nb][0] * s, acc[mt][nb][1] * s, h0, l0);
                split2h(acc[mt][nb][2] * s, acc[mt][nb][3] * s, h1, l1);
                *(uint32_t*)(Ch + (size_t)row * N + col)       = h0;
                *(uint32_t*)(Ch + (size_t)(row + 8) * N + col) = h1;
                if (isq) {
                    *(uint32_t*)(Cl + (size_t)row * N + col)       = l0;
                    *(uint32_t*)(Cl + (size_t)(row + 8) * N + col) = l1;
                }
            }
    }
}

// ---------------------------------------------------------------------------
// Tensor-core causal flash attention, fp16.
// scores: (Qh+Ql) · K   (Q pre-scaled, split; K single)   — 2 MMAs/frag
// PV:     P · V         (P, V single fp16)                — 1 MMA/frag
// BQ=128 (8 warps x 16 rows), BK=64, K/V double-buffered cp.async.
// ---------------------------------------------------------------------------
#define ASTR    272                    // 128 fp16 (256B) + 16B pad
#define QTILE_B (128 * ASTR)           // 34816
#define KVTILE  (64 * ASTR)            // 17408
#define KVSTAGE (2 * KVTILE)           // 34816 (K + V)
#define OFF_KV  (2 * QTILE_B)          // 69632
#define ATTN_SMEM_B (OFF_KV + 2 * KVSTAGE)   // 139264

__global__ __launch_bounds__(256, 1)
void attn_mma(const __half* __restrict__ qh, const __half* __restrict__ ql,
              __half* __restrict__ oh)
{
    extern __shared__ char smx[];
    const uint32_t sb = smem_u32(smx);

    const int t = threadIdx.x, w = t >> 5, lane = t & 31;
    const int qtile = (int)gridDim.x - 1 - (int)blockIdx.x;
    const int bh = blockIdx.y;
    const int b = bh >> 4, h = bh & 15;
    const int qt0 = qtile * 128;
    const int wm = w * 16;

    // ---- issue Q (hi+lo, pre-scaled) ----
    {
        const int seg = t & 15, r0 = t >> 4;
#pragma unroll
        for (int i = 0; i < 16; ++i) {
            const int tile = i >> 3;               // 0=hi, 1=lo
            const int row = (i & 7) * 16 + r0;
            const __half* src = (tile ? ql : qh)
                + (size_t)(b * S_LEN + qt0 + row) * D3 + h * DH + seg * 8;
            cp16(sb + tile * QTILE_B + row * ASTR + seg * 16, src);
        }
    }

    auto kv_load = [&](int kt, int s) {
        const int seg = t & 15, r0 = t >> 4;
        const uint32_t sbase = sb + OFF_KV + s * KVSTAGE;
#pragma unroll
        for (int i = 0; i < 8; ++i) {
            const int tile = i >> 2;               // 0=K, 1=V
            const int row = (i & 3) * 16 + r0;
            const __half* src = qh
                + (size_t)(b * S_LEN + kt * 64 + row) * D3
                + D_OUT + tile * D_OUT + h * DH + seg * 8;
            cp16(sbase + tile * KVTILE + row * ASTR + seg * 16, src);
        }
    };

    kv_load(0, 0);
    CP_COMMIT();

    const uint32_t qbh = sb + (uint32_t)(wm + (lane & 15)) * ASTR + (lane >> 4) * 16;
    const uint32_t qbl = qbh + QTILE_B;
    const uint32_t klo = (uint32_t)(lane & 15) * ASTR + (lane >> 4) * 16;
    const uint32_t vlo = (uint32_t)(((lane >> 4) << 3) + (lane & 7)) * ASTR
                         + ((lane >> 3) & 1) * 16;

    float o[16][4];
#pragma unroll
    for (int nb = 0; nb < 16; ++nb)
#pragma unroll
        for (int e = 0; e < 4; ++e) o[nb][e] = 0.f;
    float m_a = -1e30f, m_b = -1e30f, l_a = 0.f, l_b = 0.f;

    const int row_a = qt0 + wm + (lane >> 2);
    const int row_b = row_a + 8;

    const int nkt = (qt0 + 128) / 64;
    for (int kt = 0; kt < nkt; ++kt) {
        if (kt + 1 < nkt) {
            kv_load(kt + 1, (kt + 1) & 1);
            CP_COMMIT();
            CP_WAIT(1);
        } else {
            CP_WAIT(0);
        }
        __syncthreads();

        if (kt * 64 <= qt0 + wm + 15) {
            const uint32_t stb = sb + OFF_KV + (kt & 1) * KVSTAGE;
            const uint32_t kb = stb + klo;
            const uint32_t vb = stb + KVTILE + vlo;

            // ---- scores ----
            float sacc[8][4];
#pragma unroll
            for (int nb = 0; nb < 8; ++nb)
#pragma unroll
                for (int e = 0; e < 4; ++e) sacc[nb][e] = 0.f;

#pragma unroll
            for (int ks = 0; ks < 8; ++ks) {
                uint32_t ah[4], al[4];
                ldsm4(ah, qbh + ks * 32);
                ldsm4(al, qbl + ks * 32);
#pragma unroll
                for (int pg = 0; pg < 4; ++pg) {
                    uint32_t bk[4];
                    ldsm4(bk, kb + pg * 16 * ASTR + ks * 32);
                    mma_f16(sacc[pg * 2],     ah, bk[0], bk[2]);
                    mma_f16(sacc[pg * 2],     al, bk[0], bk[2]);
                    mma_f16(sacc[pg * 2 + 1], ah, bk[1], bk[3]);
                    mma_f16(sacc[pg * 2 + 1], al, bk[1], bk[3]);
                }
            }

            // ---- causal mask ----
            if (kt * 64 + 63 > qt0 + wm) {
#pragma unroll
                for (int nb = 0; nb < 8; ++nb) {
                    const int col = kt * 64 + nb * 8 + (lane & 3) * 2;
                    if (col > row_a)     sacc[nb][0] = -1e30f;
                    if (col + 1 > row_a) sacc[nb][1] = -1e30f;
                    if (col > row_b)     sacc[nb][2] = -1e30f;
                    if (col + 1 > row_b) sacc[nb][3] = -1e30f;
                }
            }

            // ---- online softmax ----
            float mx_a = -1e30f, mx_b = -1e30f;
#pragma unroll
            for (int nb = 0; nb < 8; ++nb) {
                mx_a = fmaxf(mx_a, fmaxf(sacc[nb][0], sacc[nb][1]));
                mx_b = fmaxf(mx_b, fmaxf(sacc[nb][2], sacc[nb][3]));
            }
            mx_a = fmaxf(mx_a, __shfl_xor_sync(0xffffffffu, mx_a, 1));
            mx_a = fmaxf(mx_a, __shfl_xor_sync(0xffffffffu, mx_a, 2));
            mx_b = fmaxf(mx_b, __shfl_xor_sync(0xffffffffu, mx_b, 1));
            mx_b = fmaxf(mx_b, __shfl_xor_sync(0xffffffffu, mx_b, 2));

            const float mn_a = fmaxf(m_a, mx_a);
            const float mn_b = fmaxf(m_b, mx_b);
            const float al_a = __expf(m_a - mn_a);
            const float al_b = __expf(m_b - mn_b);
            m_a = mn_a; m_b = mn_b;

            float sum_a = 0.f, sum_b = 0.f;
#pragma unroll
            for (int nb = 0; nb < 8; ++nb) {
                sacc[nb][0] = __expf(sacc[nb][0] - mn_a);
                sacc[nb][1] = __expf(sacc[nb][1] - mn_a);
                sacc[nb][2] = __expf(sacc[nb][2] - mn_b);
                sacc[nb][3] = __expf(sacc[nb][3] - mn_b);
                sum_a += sacc[nb][0] + sacc[nb][1];
                sum_b += sacc[nb][2] + sacc[nb][3];
            }
            sum_a += __shfl_xor_sync(0xffffffffu, sum_a, 1);
            sum_a += __shfl_xor_sync(0xffffffffu, sum_a, 2);
            sum_b += __shfl_xor_sync(0xffffffffu, sum_b, 1);
            sum_b += __shfl_xor_sync(0xffffffffu, sum_b, 2);
            l_a = l_a * al_a + sum_a;
            l_b = l_b * al_b + sum_b;

#pragma unroll
            for (int nb = 0; nb < 16; ++nb) {
                o[nb][0] *= al_a; o[nb][1] *= al_a;
                o[nb][2] *= al_b; o[nb][3] *= al_b;
            }

            // ---- PV: P single fp16, V single fp16 ----
#pragma unroll
            for (int kc = 0; kc < 4; ++kc) {
                uint32_t p[4];
                p[0] = packh2(sacc[2 * kc][0],     sacc[2 * kc][1]);
                p[1] = packh2(sacc[2 * kc][2],     sacc[2 * kc][3]);
                p[2] = packh2(sacc[2 * kc + 1][0], sacc[2 * kc + 1][1]);
                p[3] = packh2(sacc[2 * kc + 1][2], sacc[2 * kc + 1][3]);
#pragma unroll
                for (int pg = 0; pg < 8; ++pg) {
                    uint32_t vv[4];
                    ldsm4t(vv, vb + kc * 16 * ASTR + pg * 32);
                    mma_f16(o[pg * 2],     p, vv[0], vv[2]);
                    mma_f16(o[pg * 2 + 1], p, vv[1], vv[3]);
                }
            }
        }
        __syncthreads();
    }

    // ---- epilogue: single fp16 output ----
    const float inv_a = 1.f / l_a;
    const float inv_b = 1.f / l_b;
    const size_t oa = (size_t)(b * S_LEN + row_a) * D_OUT + h * DH;
    const size_t ob = (size_t)(b * S_LEN + row_b) * D_OUT + h * DH;
#pragma unroll
    for (int nb = 0; nb < 16; ++nb) {
        const int col = nb * 8 + (lane & 3) * 2;
        *(uint32_t*)(oh + oa + col) = packh2(o[nb][0] * inv_a, o[nb][1] * inv_a);
        *(uint32_t*)(oh + ob + col) = packh2(o[nb][2] * inv_b, o[nb][3] * inv_b);
    }
}

// ---------------------------------------------------------------------------
// Launch
// ---------------------------------------------------------------------------
extern "C" void kernel_launch(void* const* d_in, const int* in_sizes, int n_in,
                              void* d_out, int out_size)
{
    const float* x      = (const float*)d_in[0];
    const float* w_qkv  = (const float*)d_in[1];
    const float* w_proj = (const float*)d_in[2];
    const float* b_proj = (const float*)d_in[3];
    float* out = (float*)d_out;

    void *x16, *wqh, *wql, *wph, *wpl, *qkvh, *qkvl, *a16;
    cudaGetSymbolAddress(&x16, g_x16);
    cudaGetSymbolAddress(&wqh, g_wqh); cudaGetSymbolAddress(&wql, g_wql);
    cudaGetSymbolAddress(&wph, g_wph); cudaGetSymbolAddress(&wpl, g_wpl);
    cudaGetSymbolAddress(&qkvh, g_qkvh); cudaGetSymbolAddress(&qkvl, g_qkvl);
    cudaGetSymbolAddress(&a16, g_a16);

    cudaFuncSetAttribute(mma_gemm, cudaFuncAttributeMaxDynamicSharedMemorySize, GEMM_SMEM);
    cudaFuncSetAttribute(attn_mma, cudaFuncAttributeMaxDynamicSharedMemorySize, ATTN_SMEM_B);

    // 0) conversions
    {
        int n4;
        n4 = M_TOK * D_IN / 4;
        tohalf_k<<<(n4 + 255) / 256, 256>>>((const float4*)x, (uint2*)x16, n4);
        n4 = D3 * D_IN / 4;
        splith_k<<<(n4 + 255) / 256, 256>>>((const float4*)w_qkv, (uint2*)wqh, (uint2*)wql, n4);
        n4 = D_OUT * D_OUT / 4;
        splith_k<<<(n4 + 255) / 256, 256>>>((const float4*)w_proj, (uint2*)wph, (uint2*)wpl, n4);
    }

    // 1) QKV projection -> split fp16 qkv (Q cols pre-scaled)
    mma_gemm<<<dim3(D3 / 128, M_TOK / 128), 256, GEMM_SMEM>>>(
        (const __half*)x16, (const __half*)wqh, (const __half*)wql,
        nullptr, nullptr, (__half*)qkvh, (__half*)qkvl,
        M_TOK, D3, D_IN, QSCALE, D_OUT);

    // 2) Fused causal attention -> single fp16
    attn_mma<<<dim3(S_LEN / 128, B_SZ * NHEAD), 256, ATTN_SMEM_B>>>(
        (const __half*)qkvh, (const __half*)qkvl, (__half*)a16);

    // 3) Output projection + bias -> f32 out
    mma_gemm<<<dim3(D_OUT / 128, M_TOK / 128), 256, GEMM_SMEM>>>(
        (const __half*)a16, (const __half*)wph, (const __half*)wpl,
        b_proj, out, nullptr, nullptr,
        M_TOK, D_OUT, D_OUT, 1.f, 0);
}